// round 6
// baseline (speedup 1.0000x reference)
#include <cuda_runtime.h>
#include <cuda_bf16.h>
#include <cstdint>

#define Bb 2
#define Tt 4096
#define Cc 768
#define Hh 12
#define Dd 64

#define NTOK   (Bb * Tt)          // 8192
#define RSB    144                // padded smem row stride: 128B data + 16B
#define ASTG   36864              // attn stage bytes
#define SCL    0.18033688011112042f   // (1/sqrt(64)) * log2(e)

// ---------------------------------------------------------------------------
// Scratch (device globals)
// ---------------------------------------------------------------------------
__device__ __nv_bfloat16 g_xh[(size_t)NTOK * Cc], g_xl[(size_t)NTOK * Cc];
__device__ __nv_bfloat16 g_qh[(size_t)Bb * Hh * Tt * Dd], g_ql[(size_t)Bb * Hh * Tt * Dd];
__device__ __nv_bfloat16 g_kh[(size_t)Bb * Hh * Tt * Dd], g_kl[(size_t)Bb * Hh * Tt * Dd];
__device__ __nv_bfloat16 g_vh[(size_t)Bb * Hh * Tt * Dd], g_vl[(size_t)Bb * Hh * Tt * Dd];
__device__ __nv_bfloat16 g_yh[(size_t)NTOK * Cc], g_yl[(size_t)NTOK * Cc];
__device__ __nv_bfloat16 g_wqkvT_hi[(size_t)3 * Cc * Cc], g_wqkvT_lo[(size_t)3 * Cc * Cc];
__device__ __nv_bfloat16 g_woutT_hi[(size_t)Cc * Cc],     g_woutT_lo[(size_t)Cc * Cc];

// ---------------------------------------------------------------------------
// Helpers
// ---------------------------------------------------------------------------
__device__ __forceinline__ uint32_t smem_u32(const void* p) {
    uint32_t a;
    asm("{ .reg .u64 t; cvta.to.shared.u64 t, %1; cvt.u32.u64 %0, t; }" : "=r"(a) : "l"(p));
    return a;
}
__device__ __forceinline__ void ldsm4(uint32_t r[4], uint32_t a) {
    asm volatile("ldmatrix.sync.aligned.m8n8.x4.shared.b16 {%0,%1,%2,%3}, [%4];"
                 : "=r"(r[0]), "=r"(r[1]), "=r"(r[2]), "=r"(r[3]) : "r"(a));
}
__device__ __forceinline__ void ldsm4t(uint32_t r[4], uint32_t a) {
    asm volatile("ldmatrix.sync.aligned.m8n8.x4.trans.shared.b16 {%0,%1,%2,%3}, [%4];"
                 : "=r"(r[0]), "=r"(r[1]), "=r"(r[2]), "=r"(r[3]) : "r"(a));
}
__device__ __forceinline__ void mma16816(float* c, const uint32_t* a, const uint32_t* b) {
    asm volatile("mma.sync.aligned.m16n8k16.row.col.f32.bf16.bf16.f32 "
                 "{%0,%1,%2,%3}, {%4,%5,%6,%7}, {%8,%9}, {%0,%1,%2,%3};"
                 : "+f"(c[0]), "+f"(c[1]), "+f"(c[2]), "+f"(c[3])
                 : "r"(a[0]), "r"(a[1]), "r"(a[2]), "r"(a[3]), "r"(b[0]), "r"(b[1]));
}
__device__ __forceinline__ float ex2(float x) {
    float y; asm("ex2.approx.f32 %0, %1;" : "=f"(y) : "f"(x)); return y;
}
__device__ __forceinline__ uint32_t bfbits(__nv_bfloat162 v) {
    uint32_t u; *(reinterpret_cast<__nv_bfloat162*>(&u)) = v; return u;
}
__device__ __forceinline__ void split2(float a, float b, uint32_t& hi, uint32_t& lo) {
    __nv_bfloat162 h = __floats2bfloat162_rn(a, b);
    __nv_bfloat162 l = __floats2bfloat162_rn(a - __bfloat162float(h.x),
                                             b - __bfloat162float(h.y));
    hi = bfbits(h); lo = bfbits(l);
}
__device__ __forceinline__ void cpa16(uint32_t dst, const void* src) {
    asm volatile("cp.async.cg.shared.global [%0], [%1], 16;" :: "r"(dst), "l"(src));
}
#define CP_COMMIT() asm volatile("cp.async.commit_group;" ::: "memory")
#define CP_WAIT(n)  asm volatile("cp.async.wait_group %0;" :: "n"(n) : "memory")

// ---------------------------------------------------------------------------
// Prep kernels
// ---------------------------------------------------------------------------
__global__ __launch_bounds__(256) void transpose_split(const float* __restrict__ W,
                                                       __nv_bfloat16* __restrict__ Thi,
                                                       __nv_bfloat16* __restrict__ Tlo,
                                                       int K, int N) {
    __shared__ float tile[32][33];
    int n0 = blockIdx.x * 32, k0 = blockIdx.y * 32;
    int tx = threadIdx.x, ty = threadIdx.y;
#pragma unroll
    for (int i = 0; i < 4; i++)
        tile[ty + i * 8][tx] = W[(size_t)(k0 + ty + i * 8) * N + n0 + tx];
    __syncthreads();
#pragma unroll
    for (int i = 0; i < 4; i++) {
        float v = tile[tx][ty + i * 8];
        __nv_bfloat16 h = __float2bfloat16(v);
        __nv_bfloat16 l = __float2bfloat16(v - __bfloat162float(h));
        size_t o = (size_t)(n0 + ty + i * 8) * K + k0 + tx;
        Thi[o] = h; Tlo[o] = l;
    }
}

__global__ __launch_bounds__(256) void split_x(const float* __restrict__ X,
                                               __nv_bfloat16* __restrict__ Xh,
                                               __nv_bfloat16* __restrict__ Xl) {
    int i = blockIdx.x * 256 + threadIdx.x;
    float4 v = ((const float4*)X)[i];
    uint32_t h01, l01, h23, l23;
    split2(v.x, v.y, h01, l01);
    split2(v.z, v.w, h23, l23);
    ((uint2*)Xh)[i] = make_uint2(h01, h23);
    ((uint2*)Xl)[i] = make_uint2(l01, l23);
}

// ---------------------------------------------------------------------------
// HMMA bf16x3 GEMM (templated): block 128xBN, BK=64, 8 warps of WMx64,
// NSTG-stage single-sync cp.async pipeline.
// Stage layout: Ah 0, Al 18432, Bh 36864, Bl 36864+BN*RSB.
// MODE 0: qkv epilogue -> split head-major Q(scaled)/K/V.  MODE 1: fp32 C.
// ---------------------------------------------------------------------------
template<int BN, int WM, int NSTG, int MODE>
__global__ __launch_bounds__(256, 1) void gemm_hmma(
    const __nv_bfloat16* __restrict__ Ah, const __nv_bfloat16* __restrict__ Al,
    const __nv_bfloat16* __restrict__ Wh, const __nv_bfloat16* __restrict__ Wl,
    float* __restrict__ Cout,
    __nv_bfloat16* __restrict__ Qh, __nv_bfloat16* __restrict__ Ql,
    __nv_bfloat16* __restrict__ Kh, __nv_bfloat16* __restrict__ Kl,
    __nv_bfloat16* __restrict__ Vh, __nv_bfloat16* __restrict__ Vl,
    int M, int N, int K) {
    constexpr int NWM = 128 / WM;          // warps along M
    constexpr int MT  = WM / 16;           // 16-row subtiles per warp
    constexpr int BSZ = BN * RSB;          // one B half
    constexpr int SSZ = 2 * 18432 + 2 * BSZ;
    extern __shared__ __align__(128) char sm[];
    const int tid = threadIdx.x, lane = tid & 31, wid = tid >> 5;
    const int wm = (wid % NWM) * WM, wn = (wid / NWM) * 64;
    const int crow = blockIdx.y * 128, ccol = blockIdx.x * BN;
    const uint32_t sb = smem_u32(sm);
    const int nch = K / 64;

    float acc[MT][8][4];
#pragma unroll
    for (int i = 0; i < MT; i++)
#pragma unroll
        for (int j = 0; j < 8; j++)
#pragma unroll
            for (int e = 0; e < 4; e++) acc[i][j][e] = 0.f;

    auto STAGE = [&](int c, int s) {
        uint32_t sbuf = sb + (uint32_t)s * SSZ;
        const __nv_bfloat16* a0 = Ah + (size_t)crow * K + c * 64;
        const __nv_bfloat16* a1 = Al + (size_t)crow * K + c * 64;
        const __nv_bfloat16* b0 = Wh + (size_t)ccol * K + c * 64;
        const __nv_bfloat16* b1 = Wl + (size_t)ccol * K + c * 64;
#pragma unroll
        for (int i = 0; i < 4; i++) {
            int idx = tid + i * 256, r = idx >> 3, ch = idx & 7;
            size_t go = (size_t)r * K + ch * 8;
            uint32_t so = (uint32_t)(r * RSB + ch * 16);
            cpa16(sbuf + so,         a0 + go);
            cpa16(sbuf + 18432 + so, a1 + go);
        }
#pragma unroll
        for (int i = 0; i < BN / 32; i++) {
            int idx = tid + i * 256, r = idx >> 3, ch = idx & 7;
            size_t go = (size_t)r * K + ch * 8;
            uint32_t so = (uint32_t)(r * RSB + ch * 16);
            cpa16(sbuf + 36864 + so,       b0 + go);
            cpa16(sbuf + 36864 + BSZ + so, b1 + go);
        }
    };
    auto MMAC = [&](int s) {
        const uint32_t sA = sb + (uint32_t)s * SSZ;
        const uint32_t sB = sA + 36864;
#pragma unroll
        for (int ks = 0; ks < 4; ks++) {
            uint32_t ah[MT][4], al[MT][4];
#pragma unroll
            for (int mt = 0; mt < MT; mt++) {
                uint32_t ad = sA + (uint32_t)((wm + mt * 16 + (lane & 15)) * RSB +
                                              ks * 32 + ((lane & 16) ? 16 : 0));
                ldsm4(ah[mt], ad);
                ldsm4(al[mt], ad + 18432);
            }
#pragma unroll
            for (int q = 0; q < 4; q++) {
                uint32_t bd = sB + (uint32_t)((wn + q * 16 + (lane & 7) + ((lane >> 4) << 3)) * RSB +
                                              ks * 32 + ((lane & 8) ? 16 : 0));
                uint32_t bh[4], bl[4];
                ldsm4(bh, bd);
                ldsm4(bl, bd + BSZ);
#pragma unroll
                for (int mt = 0; mt < MT; mt++) {
                    mma16816(acc[mt][2 * q],     ah[mt], bh);
                    mma16816(acc[mt][2 * q],     al[mt], bh);
                    mma16816(acc[mt][2 * q],     ah[mt], bl);
                    mma16816(acc[mt][2 * q + 1], ah[mt], bh + 2);
                    mma16816(acc[mt][2 * q + 1], al[mt], bh + 2);
                    mma16816(acc[mt][2 * q + 1], ah[mt], bl + 2);
                }
            }
        }
    };

#pragma unroll
    for (int s = 0; s < NSTG - 1; s++) { STAGE(s, s); CP_COMMIT(); }
    for (int c = 0; c < nch; c++) {
        CP_WAIT(NSTG - 2);
        __syncthreads();
        if (c + NSTG - 1 < nch) STAGE(c + NSTG - 1, (c + NSTG - 1) % NSTG);
        CP_COMMIT();
        MMAC(c % NSTG);
    }

    if (MODE == 1) {
#pragma unroll
        for (int mt = 0; mt < MT; mt++)
#pragma unroll
            for (int nt = 0; nt < 8; nt++) {
                int row = crow + wm + mt * 16 + (lane >> 2);
                int col = ccol + wn + nt * 8 + (lane & 3) * 2;
                *(float2*)(Cout + (size_t)row * N + col) =
                    make_float2(acc[mt][nt][0], acc[mt][nt][1]);
                *(float2*)(Cout + (size_t)(row + 8) * N + col) =
                    make_float2(acc[mt][nt][2], acc[mt][nt][3]);
            }
    } else {
        __nv_bfloat16* PH[3] = {Qh, Kh, Vh};
        __nv_bfloat16* PL[3] = {Ql, Kl, Vl};
        const int selb = ccol / Cc;           // BN divides Cc boundaries
        const float scale = (selb == 0) ? SCL : 1.f;
        __nv_bfloat16* ph = PH[selb];
        __nv_bfloat16* pl = PL[selb];
#pragma unroll
        for (int mt = 0; mt < MT; mt++)
#pragma unroll
            for (int nt = 0; nt < 8; nt++) {
                int row = crow + wm + mt * 16 + (lane >> 2);
                int col = ccol + wn + nt * 8 + (lane & 3) * 2;
                int rem = col - selb * Cc, h = rem >> 6, d = rem & 63;
#pragma unroll
                for (int half = 0; half < 2; half++) {
                    int r2 = row + half * 8;
                    int b = r2 >> 12, t = r2 & 4095;
                    size_t off = ((size_t)(b * Hh + h) * Tt + t) * Dd + d;
                    uint32_t hi, lo;
                    split2(acc[mt][nt][2 * half] * scale,
                           acc[mt][nt][2 * half + 1] * scale, hi, lo);
                    *(uint32_t*)(ph + off) = hi;
                    *(uint32_t*)(pl + off) = lo;
                }
            }
    }
}

// ---------------------------------------------------------------------------
// HMMA causal flash attention, FA2-style pipelined: PV of tile kt-1 issued
// between QK(kt) and softmax(kt) so softmax ALU overlaps tensor work.
// 128 q-rows/CTA (8 warps x 16), 64-key tiles, 4-stage cp.async K/V ring.
// ---------------------------------------------------------------------------
__global__ __launch_bounds__(256, 1) void attn_hmma(
    const __nv_bfloat16* __restrict__ Qh_, const __nv_bfloat16* __restrict__ Ql_,
    const __nv_bfloat16* __restrict__ Kh_, const __nv_bfloat16* __restrict__ Kl_,
    const __nv_bfloat16* __restrict__ Vh_, const __nv_bfloat16* __restrict__ Vl_,
    __nv_bfloat16* __restrict__ Yh, __nv_bfloat16* __restrict__ Yl) {
    extern __shared__ __align__(128) char sm[];
    const int tid = threadIdx.x, lane = tid & 31, wid = tid >> 5;
    const int bh = blockIdx.y, b = bh / Hh, h = bh % Hh;
    const int qt = (int)gridDim.x - 1 - (int)blockIdx.x;   // big tiles first
    const int q0 = qt * 128;
    const int m0 = wid * 16;
    const uint32_t sb = smem_u32(sm);
    const size_t hb = (size_t)bh * Tt;

    // ---- stage Q (pre-scaled, pre-split) transiently; load fragments ----
    {
        const __nv_bfloat16* qg0 = Qh_ + (hb + q0) * Dd;
        const __nv_bfloat16* qg1 = Ql_ + (hb + q0) * Dd;
#pragma unroll
        for (int i = 0; i < 4; i++) {
            int idx = tid + i * 256, r = idx >> 3, ch = idx & 7;
            *(uint4*)(sm + r * RSB + ch * 16)         = *(const uint4*)(qg0 + r * Dd + ch * 8);
            *(uint4*)(sm + 18432 + r * RSB + ch * 16) = *(const uint4*)(qg1 + r * Dd + ch * 8);
        }
    }
    __syncthreads();
    uint32_t qh[4][4], ql[4][4];
#pragma unroll
    for (int ks = 0; ks < 4; ks++) {
        uint32_t ad = sb + (uint32_t)((m0 + (lane & 15)) * RSB + ks * 32 + ((lane & 16) ? 16 : 0));
        ldsm4(qh[ks], ad);
        ldsm4(ql[ks], ad + 18432);
    }
    __syncthreads();

    auto STAGEKV = [&](int kt, int s) {
        uint32_t sbuf = sb + (uint32_t)s * ASTG;
        const __nv_bfloat16* k0 = Kh_ + (hb + kt * 64) * Dd;
        const __nv_bfloat16* k1 = Kl_ + (hb + kt * 64) * Dd;
        const __nv_bfloat16* v0 = Vh_ + (hb + kt * 64) * Dd;
        const __nv_bfloat16* v1 = Vl_ + (hb + kt * 64) * Dd;
#pragma unroll
        for (int i = 0; i < 2; i++) {
            int idx = tid + i * 256, r = idx >> 3, ch = idx & 7;
            size_t go = (size_t)r * Dd + ch * 8;
            uint32_t so = (uint32_t)(r * RSB + ch * 16);
            cpa16(sbuf + so,         k0 + go);
            cpa16(sbuf + 9216 + so,  k1 + go);
            cpa16(sbuf + 18432 + so, v0 + go);
            cpa16(sbuf + 27648 + so, v1 + go);
        }
    };

    auto PV = [&](float o[8][4], const uint32_t* ph, const uint32_t* ph8,
                  const uint32_t* pl, const uint32_t* pl8, uint32_t vbase) {
#pragma unroll
        for (int kk = 0; kk < 4; kk++) {
            uint32_t ah4[4] = {ph[2 * kk], ph8[2 * kk], ph[2 * kk + 1], ph8[2 * kk + 1]};
            uint32_t al4[4] = {pl[2 * kk], pl8[2 * kk], pl[2 * kk + 1], pl8[2 * kk + 1]};
#pragma unroll
            for (int q2 = 0; q2 < 4; q2++) {
                uint32_t vd = vbase + 18432u + (uint32_t)((kk * 16 + (lane & 15)) * RSB +
                                                          (q2 * 16 + ((lane & 16) ? 8 : 0)) * 2);
                uint32_t vh4[4], vl4[4];
                ldsm4t(vh4, vd);
                ldsm4t(vl4, vd + 9216);
                mma16816(o[2 * q2],     ah4, vh4);
                mma16816(o[2 * q2],     al4, vh4);
                mma16816(o[2 * q2],     ah4, vl4);
                mma16816(o[2 * q2 + 1], ah4, vh4 + 2);
                mma16816(o[2 * q2 + 1], al4, vh4 + 2);
                mma16816(o[2 * q2 + 1], ah4, vl4 + 2);
            }
        }
    };

    float o[8][4];
#pragma unroll
    for (int j = 0; j < 8; j++)
#pragma unroll
        for (int e = 0; e < 4; e++) o[j][e] = 0.f;
    float m1 = -1e30f, m2 = -1e30f, l1 = 0.f, l2 = 0.f;
    uint32_t ph[8], pl[8], ph8[8], pl8[8];
    bool prev = false;
    uint32_t pvb = 0;
    const int nkt = 2 * qt + 2;

    STAGEKV(0, 0); CP_COMMIT();
    STAGEKV(1, 1); CP_COMMIT();

    for (int kt = 0; kt < nkt; kt++) {
        CP_WAIT(1);
        __syncthreads();                    // stage kt ready; kt-2 reads done
        if (kt + 2 < nkt) STAGEKV(kt + 2, (kt + 2) & 3);
        CP_COMMIT();
        const uint32_t sbuf = sb + (uint32_t)(kt & 3) * ASTG;
        const bool cur = (kt * 64 <= q0 + m0 + 15);

        // ---- S = Q @ K^T (bf16x3), tensor ----
        float cS[8][4];
        if (cur) {
#pragma unroll
            for (int j = 0; j < 8; j++)
#pragma unroll
                for (int e = 0; e < 4; e++) cS[j][e] = 0.f;
#pragma unroll
            for (int ks = 0; ks < 4; ks++) {
#pragma unroll
                for (int q2 = 0; q2 < 4; q2++) {
                    uint32_t bd = sbuf + (uint32_t)((q2 * 16 + (lane & 7) + ((lane >> 4) << 3)) * RSB +
                                                    ks * 32 + ((lane & 8) ? 16 : 0));
                    uint32_t kh4[4], kl4[4];
                    ldsm4(kh4, bd);
                    ldsm4(kl4, bd + 9216);
                    mma16816(cS[2 * q2],     qh[ks], kh4);
                    mma16816(cS[2 * q2],     ql[ks], kh4);
                    mma16816(cS[2 * q2],     qh[ks], kl4);
                    mma16816(cS[2 * q2 + 1], qh[ks], kh4 + 2);
                    mma16816(cS[2 * q2 + 1], ql[ks], kh4 + 2);
                    mma16816(cS[2 * q2 + 1], qh[ks], kl4 + 2);
                }
            }
        }

        // ---- O += P(kt-1) @ V(kt-1): fills tensor pipe under softmax below ----
        if (prev) PV(o, ph, ph8, pl, pl8, pvb);

        if (cur) {
            // ---- causal mask ----
            if (kt >= 2 * qt) {
                int r1 = q0 + m0 + (lane >> 2);
#pragma unroll
                for (int nt = 0; nt < 8; nt++) {
                    int k0c = kt * 64 + nt * 8 + (lane & 3) * 2;
                    if (k0c     > r1)     cS[nt][0] = -1e30f;
                    if (k0c + 1 > r1)     cS[nt][1] = -1e30f;
                    if (k0c     > r1 + 8) cS[nt][2] = -1e30f;
                    if (k0c + 1 > r1 + 8) cS[nt][3] = -1e30f;
                }
            }
            // ---- softmax (o-rescale last, after PV drains) ----
            float mx1 = -1e30f, mx2 = -1e30f;
#pragma unroll
            for (int nt = 0; nt < 8; nt++) {
                mx1 = fmaxf(mx1, fmaxf(cS[nt][0], cS[nt][1]));
                mx2 = fmaxf(mx2, fmaxf(cS[nt][2], cS[nt][3]));
            }
            mx1 = fmaxf(mx1, __shfl_xor_sync(0xffffffffu, mx1, 1));
            mx1 = fmaxf(mx1, __shfl_xor_sync(0xffffffffu, mx1, 2));
            mx2 = fmaxf(mx2, __shfl_xor_sync(0xffffffffu, mx2, 1));
            mx2 = fmaxf(mx2, __shfl_xor_sync(0xffffffffu, mx2, 2));
            float mn1 = fmaxf(m1, mx1), mn2 = fmaxf(m2, mx2);
            float a1 = ex2(m1 - mn1), a2 = ex2(m2 - mn2);
            float s1 = 0.f, s2 = 0.f;
#pragma unroll
            for (int nt = 0; nt < 8; nt++) {
                float p0 = ex2(cS[nt][0] - mn1), p1 = ex2(cS[nt][1] - mn1);
                float p2 = ex2(cS[nt][2] - mn2), p3 = ex2(cS[nt][3] - mn2);
                s1 += p0 + p1;
                s2 += p2 + p3;
                split2(p0, p1, ph[nt], pl[nt]);
                split2(p2, p3, ph8[nt], pl8[nt]);
            }
            s1 += __shfl_xor_sync(0xffffffffu, s1, 1);
            s1 += __shfl_xor_sync(0xffffffffu, s1, 2);
            s2 += __shfl_xor_sync(0xffffffffu, s2, 1);
            s2 += __shfl_xor_sync(0xffffffffu, s2, 2);
            l1 = l1 * a1 + s1;
            l2 = l2 * a2 + s2;
#pragma unroll
            for (int nt = 0; nt < 8; nt++) {
                o[nt][0] *= a1; o[nt][1] *= a1;
                o[nt][2] *= a2; o[nt][3] *= a2;
            }
            m1 = mn1;
            m2 = mn2;
        }
        prev = cur;
        pvb = sbuf;
    }
    if (prev) PV(o, ph, ph8, pl, pl8, pvb);   // drain last tile

    // ---- epilogue: O /= l, split, store y (token-major) ----
    float i1 = 1.f / l1, i2 = 1.f / l2;
    int row = q0 + m0 + (lane >> 2);
#pragma unroll
    for (int nt = 0; nt < 8; nt++) {
        int col = h * Dd + nt * 8 + (lane & 3) * 2;
        size_t off1 = ((size_t)b * Tt + row) * Cc + col;
        size_t off2 = off1 + (size_t)8 * Cc;
        uint32_t hi, lo;
        split2(o[nt][0] * i1, o[nt][1] * i1, hi, lo);
        *(uint32_t*)(Yh + off1) = hi;
        *(uint32_t*)(Yl + off1) = lo;
        split2(o[nt][2] * i2, o[nt][3] * i2, hi, lo);
        *(uint32_t*)(Yh + off2) = hi;
        *(uint32_t*)(Yl + off2) = lo;
    }
}

// ---------------------------------------------------------------------------
extern "C" void kernel_launch(void* const* d_in, const int* in_sizes, int n_in,
                              void* d_out, int out_size) {
    const float* x     = (const float*)d_in[0];
    const float* w_qkv = (const float*)d_in[1];
    const float* w_out = (const float*)d_in[2];
    float* out = (float*)d_out;

    __nv_bfloat16 *xh, *xl, *qh, *ql, *kh, *kl, *vh, *vl, *yh, *yl;
    __nv_bfloat16 *wqh, *wql, *woh, *wol;
    cudaGetSymbolAddress((void**)&xh, g_xh);   cudaGetSymbolAddress((void**)&xl, g_xl);
    cudaGetSymbolAddress((void**)&qh, g_qh);   cudaGetSymbolAddress((void**)&ql, g_ql);
    cudaGetSymbolAddress((void**)&kh, g_kh);   cudaGetSymbolAddress((void**)&kl, g_kl);
    cudaGetSymbolAddress((void**)&vh, g_vh);   cudaGetSymbolAddress((void**)&vl, g_vl);
    cudaGetSymbolAddress((void**)&yh, g_yh);   cudaGetSymbolAddress((void**)&yl, g_yl);
    cudaGetSymbolAddress((void**)&wqh, g_wqkvT_hi); cudaGetSymbolAddress((void**)&wql, g_wqkvT_lo);
    cudaGetSymbolAddress((void**)&woh, g_woutT_hi); cudaGetSymbolAddress((void**)&wol, g_woutT_lo);

    // smem budgets: qkv gemm 2*(36864+2*256*144)=221184; wout 3*73728=221184; attn 4*36864
    cudaFuncSetAttribute((const void*)gemm_hmma<256, 64, 2, 0>,
                         cudaFuncAttributeMaxDynamicSharedMemorySize, 221184);
    cudaFuncSetAttribute((const void*)gemm_hmma<128, 32, 3, 1>,
                         cudaFuncAttributeMaxDynamicSharedMemorySize, 221184);
    cudaFuncSetAttribute((const void*)attn_hmma,
                         cudaFuncAttributeMaxDynamicSharedMemorySize, 4 * ASTG);

    // 0) prep
    transpose_split<<<dim3((3 * Cc) / 32, Cc / 32), dim3(32, 8)>>>(w_qkv, wqh, wql, Cc, 3 * Cc);
    transpose_split<<<dim3(Cc / 32, Cc / 32), dim3(32, 8)>>>(w_out, woh, wol, Cc, Cc);
    split_x<<<(NTOK * Cc / 4) / 256, 256>>>(x, xh, xl);

    // 1) qkv GEMM (128x256 tiles) -> split head-major Q(scaled)/K/V
    gemm_hmma<256, 64, 2, 0><<<dim3((3 * Cc) / 256, NTOK / 128), 256, 221184>>>(
        xh, xl, wqh, wql, nullptr, qh, ql, kh, kl, vh, vl, NTOK, 3 * Cc, Cc);

    // 2) causal flash attention (pipelined) -> split y
    attn_hmma<<<dim3(Tt / 128, Bb * Hh), 256, 4 * ASTG>>>(qh, ql, kh, kl, vh, vl, yh, yl);

    // 3) out = y @ w_out (128x128 tiles, fp32 out)
    gemm_hmma<128, 32, 3, 1><<<dim3(Cc / 128, NTOK / 128), 256, 221184>>>(
        yh, yl, woh, wol, out, nullptr, nullptr, nullptr, nullptr, nullptr, nullptr,
        NTOK, Cc, Cc);
}